// round 10
// baseline (speedup 1.0000x reference)
#include <cuda_runtime.h>
#include <cuda_fp16.h>
#include <math.h>
#include <stdint.h>

// ---------------- problem constants ----------------
#define BATCH 4
#define INC   32
#define OUTC  64
#define HW    56
#define PH    58
#define MTOT  (BATCH*HW*HW)              // 12544
#define NPIX  (BATCH*PH*PH)              // 13456 padded pixels
#define KSPL  2304                       // 9 taps * 256
#define KBAS  288                       // 9 taps * 32
#define NCH_S 72                         // spline chunks of k=32
#define NCH   81                         // + 9 base chunks
#define CPB   27                         // chunks per block (81/3)
#define MT    128                        // GEMM M tile

// ---------------- scratch ----------------
__device__ __half g_fh[NPIX*256];        // basis features fp16 [pix][c*8+f]
__device__ __half g_xph[NPIX*32];        // raw x fp16          [pix][c]
__device__ __half g_wsh[OUTC*KSPL];      // spline W hi [o][k]
__device__ __half g_wsl[OUTC*KSPL];      // spline W lo
__device__ __half g_wbh[OUTC*KBAS];      // base W hi   [o][k]
__device__ __half g_wbl[OUTC*KBAS];
__device__ float  g_S[3*MTOT*OUTC];      // spline split-K partials [z][m][o]
__device__ float  g_Bc[MTOT*OUTC];       // base conv result        [m][o]

// ---------------- helpers ----------------
__device__ __forceinline__ uint32_t smem_u32(const void* p) {
    uint32_t a;
    asm("{ .reg .u64 t; cvta.to.shared.u64 t, %1; cvt.u32.u64 %0, t; }" : "=r"(a) : "l"(p));
    return a;
}
#define CPA16(sm, gp) asm volatile("cp.async.cg.shared.global [%0], [%1], 16;" :: "r"(sm), "l"(gp))
#define CP_COMMIT()   asm volatile("cp.async.commit_group;" ::: "memory")
#define CP_WAIT1()    asm volatile("cp.async.wait_group 1;" ::: "memory")
#define CP_WAIT0()    asm volatile("cp.async.wait_group 0;" ::: "memory")

__device__ __forceinline__ void mma16816(float* d, const uint32_t* a, const uint32_t* b) {
    asm volatile(
        "mma.sync.aligned.m16n8k16.row.col.f32.f16.f16.f32 "
        "{%0,%1,%2,%3}, {%4,%5,%6,%7}, {%8,%9}, {%0,%1,%2,%3};"
        : "+f"(d[0]), "+f"(d[1]), "+f"(d[2]), "+f"(d[3])
        : "r"(a[0]), "r"(a[1]), "r"(a[2]), "r"(a[3]), "r"(b[0]), "r"(b[1]));
}

// ---------------- knots / bspline ----------------
__device__ __forceinline__ float knot(int i) { return (float)(i - 3) * 0.4f - 1.0f; }

__device__ __forceinline__ void bspline8(float xv, float* out8) {
    float bb[11];
#pragma unroll
    for (int i = 0; i < 11; i++)
        bb[i] = (xv >= knot(i) && xv < knot(i + 1)) ? 1.0f : 0.0f;
    const float RK1 = 2.5f, RK2 = 1.25f, RK3 = 1.0f / 1.2f;
#pragma unroll
    for (int i = 0; i < 10; i++)
        bb[i] = (xv - knot(i)) * RK1 * bb[i] + (knot(i + 2) - xv) * RK1 * bb[i + 1];
#pragma unroll
    for (int i = 0; i < 9; i++)
        bb[i] = (xv - knot(i)) * RK2 * bb[i] + (knot(i + 3) - xv) * RK2 * bb[i + 1];
#pragma unroll
    for (int i = 0; i < 8; i++)
        bb[i] = (xv - knot(i)) * RK3 * bb[i] + (knot(i + 4) - xv) * RK3 * bb[i + 1];
#pragma unroll
    for (int i = 0; i < 8; i++) out8[i] = bb[i];
}

// ---------------- kernel 1: pack weights (vectorized) ----------------
// Spline part: one thread per (o,c,tap) handles the 8 contiguous f values.
// Base part: one thread per (o,tap,c).
__global__ void pack_kernel(const float* __restrict__ sw, const float* __restrict__ bw)
{
    int t = blockIdx.x * blockDim.x + threadIdx.x;
    const int NSPL = OUTC * INC * 9;     // 18432
    const int NBAS = OUTC * KBAS;        // 18432
    if (t < NSPL) {
        int o = t / 288;
        int rem = t - o * 288;
        int c = rem / 9, tap = rem - c * 9;
        const float* src = sw + (size_t)(o * 288 + c * 9 + tap) * 8;
        float4 v0 = *(const float4*)(src);
        float4 v1 = *(const float4*)(src + 4);
        float vv[8] = {v0.x, v0.y, v0.z, v0.w, v1.x, v1.y, v1.z, v1.w};
        __half2 hh[4], hl[4];
#pragma unroll
        for (int i = 0; i < 4; i++) {
            __half h0 = __float2half_rn(vv[2 * i]);
            __half h1 = __float2half_rn(vv[2 * i + 1]);
            hh[i] = __halves2half2(h0, h1);
            hl[i] = __halves2half2(__float2half_rn(vv[2 * i] - __half2float(h0)),
                                   __float2half_rn(vv[2 * i + 1] - __half2float(h1)));
        }
        size_t dst = (size_t)o * KSPL + tap * 256 + c * 8;
        *(uint4*)(g_wsh + dst) = *(uint4*)hh;
        *(uint4*)(g_wsl + dst) = *(uint4*)hl;
    } else if (t < NSPL + NBAS) {
        int u = t - NSPL;
        int o = u / KBAS;
        int k = u - o * KBAS;            // k = tap*32 + c
        int tap = k >> 5, c = k & 31;
        float v = bw[(o * 32 + c) * 9 + tap];
        __half h = __float2half_rn(v);
        g_wbh[u] = h;
        g_wbl[u] = __float2half_rn(v - __half2float(h));
    }
}

// ---------------- kernel 2: basis fill over the PADDED grid ----------------
// Reference applies B-spline bases to padded zeros too (bases(0) != 0).
__global__ void fillpad_kernel(const float* __restrict__ x)
{
    int t = blockIdx.x * blockDim.x + threadIdx.x;
    if (t >= NPIX * 32) return;
    int c = t & 31;
    int pix = t >> 5;
    int w = pix % 58;
    int tmp = pix / 58;
    int h = tmp % 58;
    int b = tmp / 58;

    float xv = 0.0f;
    if (h >= 1 && h <= 56 && w >= 1 && w <= 56)
        xv = x[((b * 32 + c) * 56 + (h - 1)) * 56 + (w - 1)];

    float bb[8];
    bspline8(xv, bb);

    __half2 hh[4];
#pragma unroll
    for (int i = 0; i < 4; i++)
        hh[i] = __halves2half2(__float2half_rn(bb[2 * i]), __float2half_rn(bb[2 * i + 1]));
    *(uint4*)(g_fh + (size_t)pix * 256 + c * 8) = *(uint4*)hh;
    g_xph[pix * 32 + c] = __float2half_rn(xv);
}

// ---------------- kernel 3: split-K mma.sync GEMM, M-tile=128 ----------------
// grid (98, 3): 294 uniform blocks (~2/SM), each does exactly 27 k=32 chunks.
// 256 threads = 8 warps as 4M x 2N. Double-buffered cp.async.
// 2-pass compensation: rn16(A)*Bh + rn16(A)*Bl.
#define ASTRIDE 40   // halfs per smem row (80B, conflict-free)

__global__ void __launch_bounds__(256) kan_mma_kernel()
{
    __shared__ __align__(16) __half sA [2][MT * ASTRIDE];
    __shared__ __align__(16) __half sBh[2][64 * ASTRIDE];
    __shared__ __align__(16) __half sBl[2][64 * ASTRIDE];

    const int tid  = threadIdx.x;
    const int wid  = tid >> 5, lane = tid & 31;
    const int wm   = wid >> 1, wn = wid & 1;          // 4x2 warp grid
    const int g    = lane >> 2, tg = lane & 3;
    const int mBase = blockIdx.x * MT;
    const int z     = blockIdx.y;
    const int chBase = z * CPB;

    // A loader: row = tid>>1 (0..127), two 16B segs at (tid&1)*2 + {0,1}
    const int lrow = tid >> 1;
    const int lsg0 = (tid & 1) * 2;
    int lm = mBase + lrow;
    int lb = lm / 3136; int lrem = lm - lb * 3136;
    int loh = lrem / 56, low = lrem - loh * 56;
    const int ppix = (lb * 58 + loh) * 58 + low;
    const uint32_t soA = (uint32_t)(lrow * ASTRIDE + lsg0 * 8) * 2;

    // B loader: row = tid>>2 (0..63), one 16B seg at tid&3 (for Bh and Bl each)
    const int brow = tid >> 2;
    const int bsg  = tid & 3;
    const uint32_t soB = (uint32_t)(brow * ASTRIDE + bsg * 8) * 2;

    float accS[2][4][4] = {};
    float accB[2][4][4] = {};

    auto load_stage = [&](int ch, int st) {
        const __half *ga, *gb_h, *gb_l;
        if (ch < NCH_S) {
            int tap = ch >> 3;
            int cf0 = (ch & 7) * 32;
            int toff = ((tap / 3) * 58 + (tap % 3)) * 256 + cf0;
            ga   = g_fh + (size_t)ppix * 256 + toff;
            int kt = ch * 32;
            gb_h = g_wsh + brow * KSPL + kt;
            gb_l = g_wsl + brow * KSPL + kt;
        } else {
            int tap = ch - NCH_S;
            int toff = ((tap / 3) * 58 + (tap % 3)) * 32;
            ga   = g_xph + (size_t)ppix * 32 + toff;
            int kt = tap * 32;
            gb_h = g_wbh + brow * KBAS + kt;
            gb_l = g_wbl + brow * KBAS + kt;
        }
        uint32_t a  = smem_u32(&sA [st][0]) + soA;
        uint32_t bh = smem_u32(&sBh[st][0]) + soB;
        uint32_t bl = smem_u32(&sBl[st][0]) + soB;
#pragma unroll
        for (int s = 0; s < 2; s++)
            CPA16(a + s * 16, ga + (lsg0 + s) * 8);
        CPA16(bh, gb_h + bsg * 8);
        CPA16(bl, gb_l + bsg * 8);
    };

    auto do_chunk = [&](float (&acc)[2][4][4], int st) {
        const __half* A  = sA [st];
        const __half* Bh = sBh[st];
        const __half* Bl = sBl[st];
#pragma unroll
        for (int k0 = 0; k0 < 32; k0 += 16) {
            uint32_t a[2][4], bh[4][2], bl[4][2];
            const int cb = k0 + 2 * tg;
#pragma unroll
            for (int mi = 0; mi < 2; mi++) {
                int r = wm * 32 + mi * 16 + g;
                a[mi][0] = *(const uint32_t*)&A[r * ASTRIDE + cb];
                a[mi][1] = *(const uint32_t*)&A[(r + 8) * ASTRIDE + cb];
                a[mi][2] = *(const uint32_t*)&A[r * ASTRIDE + cb + 8];
                a[mi][3] = *(const uint32_t*)&A[(r + 8) * ASTRIDE + cb + 8];
            }
#pragma unroll
            for (int nj = 0; nj < 4; nj++) {
                int n = wn * 32 + nj * 8 + g;
                bh[nj][0] = *(const uint32_t*)&Bh[n * ASTRIDE + cb];
                bh[nj][1] = *(const uint32_t*)&Bh[n * ASTRIDE + cb + 8];
                bl[nj][0] = *(const uint32_t*)&Bl[n * ASTRIDE + cb];
                bl[nj][1] = *(const uint32_t*)&Bl[n * ASTRIDE + cb + 8];
            }
#pragma unroll
            for (int mi = 0; mi < 2; mi++)
#pragma unroll
                for (int nj = 0; nj < 4; nj++) {
                    mma16816(acc[mi][nj], a[mi], bh[nj]);
                    mma16816(acc[mi][nj], a[mi], bl[nj]);
                }
        }
    };

    load_stage(chBase, 0);
    CP_COMMIT();
    for (int i = 0; i < CPB; i++) {
        int ch = chBase + i;
        int st = i & 1;
        if (i + 1 < CPB) {
            load_stage(ch + 1, st ^ 1);
            CP_COMMIT();
            CP_WAIT1();
        } else {
            CP_WAIT0();
        }
        __syncthreads();
        if (ch < NCH_S) do_chunk(accS, st);
        else            do_chunk(accB, st);
        __syncthreads();
    }

    // ---- store partials [m][o]; z==2 also stores base result ----
    float* Sp = g_S + (size_t)z * MTOT * 64;
#pragma unroll
    for (int mi = 0; mi < 2; mi++) {
#pragma unroll
        for (int gg = 0; gg < 2; gg++) {
            int row = wm * 32 + mi * 16 + g + gg * 8;
            size_t m = mBase + row;
#pragma unroll
            for (int nj = 0; nj < 4; nj++) {
                int o0 = wn * 32 + nj * 8 + 2 * tg;
                *(float2*)&Sp[m * 64 + o0] =
                    make_float2(accS[mi][nj][gg * 2], accS[mi][nj][gg * 2 + 1]);
                if (z == 2)
                    *(float2*)&g_Bc[m * 64 + o0] =
                        make_float2(accB[mi][nj][gg * 2], accB[mi][nj][gg * 2 + 1]);
            }
        }
    }
}

// ---------------- kernel 4: reduce + silu + scaler epilogue ----------------
// 392 blocks x 256 threads; each block: 32 m-pixels x 64 o. smem transpose.
__global__ void __launch_bounds__(256) reduce_kernel(const float* __restrict__ scaler,
                                                     float* __restrict__ out)
{
    __shared__ float T[64][33];
    const int tid = threadIdx.x;
    const int mBase = blockIdx.x * 32;
    const int b = mBase / 3136, ssp0 = mBase - b * 3136;

    {   // phase 1: read [m][o] coalesced (two float4 per thread per array)
        const int ml = tid >> 3;              // 0..31
        const int o8 = (tid & 7) * 8;
        size_t m = mBase + ml;
#pragma unroll
        for (int jj = 0; jj < 2; jj++) {
            int o4 = o8 + jj * 4;
            float4 sc4 = *(const float4*)(scaler + o4);
            float4 s0 = *(const float4*)&g_S[m * 64 + o4];
            float4 s1 = *(const float4*)&g_S[((size_t)MTOT + m) * 64 + o4];
            float4 s2 = *(const float4*)&g_S[((size_t)2 * MTOT + m) * 64 + o4];
            float4 bv = *(const float4*)&g_Bc[m * 64 + o4];
            float ss[4] = {s0.x + s1.x + s2.x, s0.y + s1.y + s2.y,
                           s0.z + s1.z + s2.z, s0.w + s1.w + s2.w};
            float bb[4] = {bv.x, bv.y, bv.z, bv.w};
            float sv[4] = {sc4.x, sc4.y, sc4.z, sc4.w};
#pragma unroll
            for (int j = 0; j < 4; j++) {
                float silu = bb[j] / (1.0f + expf(-bb[j]));
                T[o4 + j][ml] = silu + sv[j] * ss[j];
            }
        }
    }
    __syncthreads();
    {   // phase 2: write [o][m] coalesced (two float4 per thread)
        const int o  = tid >> 2;              // 0..63
        const int ms = (tid & 3) * 8;
        float* ob = out + ((size_t)(b * 64 + o)) * 3136 + ssp0 + ms;
        *(float4*)(ob)     = make_float4(T[o][ms],     T[o][ms + 1], T[o][ms + 2], T[o][ms + 3]);
        *(float4*)(ob + 4) = make_float4(T[o][ms + 4], T[o][ms + 5], T[o][ms + 6], T[o][ms + 7]);
    }
}

// ---------------- launch ----------------
extern "C" void kernel_launch(void* const* d_in, const int* in_sizes, int n_in,
                              void* d_out, int out_size)
{
    const float* x  = (const float*)d_in[0];  // (4,32,56,56)
    const float* bw = (const float*)d_in[1];  // (64,32,3,3)
    const float* sw = (const float*)d_in[2];  // (64,288,8)
    const float* sc = (const float*)d_in[3];  // (64,)
    float* out = (float*)d_out;               // (4,64,56,56)

    {   // 1. pack weights (vectorized fp16 hi/lo, [o][k])
        int total = OUTC * INC * 9 + OUTC * KBAS;
        pack_kernel<<<(total + 255) / 256, 256>>>(sw, bw);
    }
    {   // 2. basis expansion over the padded grid
        int total = NPIX * 32;
        fillpad_kernel<<<(total + 255) / 256, 256>>>(x);
    }
    {   // 3. split-K GEMM: 294 uniform blocks (~2/SM), M-tile 128
        dim3 grid(MTOT / MT, 3);
        kan_mma_kernel<<<grid, 256>>>();
    }
    {   // 4. reduce + silu + scaler + store
        reduce_kernel<<<MTOT / 32, 256>>>(sc, out);
    }
}

// round 13
// speedup vs baseline: 1.6821x; 1.6821x over previous
#include <cuda_runtime.h>
#include <cuda_fp16.h>
#include <math.h>
#include <stdint.h>

// ---------------- problem constants ----------------
#define BATCH 4
#define INC   32
#define OUTC  64
#define HW    56
#define PH    58
#define MTOT  (BATCH*HW*HW)              // 12544
#define NPIX  (BATCH*PH*PH)              // 13456 padded pixels
#define KSPL  2304                       // 9 taps * 256
#define KBAS  288                        // 9 taps * 32
#define NCH_S 72                         // spline chunks of k=32
#define NCH   81                         // + 9 base chunks
#define CPB   27                         // chunks per block (81/3)

// ---------------- scratch ----------------
__device__ __half g_fh[NPIX*256];        // basis features fp16 [pix][c*8+f]
__device__ __half g_xph[NPIX*32];        // raw x fp16          [pix][c]
__device__ __half g_wsh[OUTC*KSPL];      // spline W fp16 [o][k]
__device__ __half g_wbh[OUTC*KBAS];      // base W fp16   [o][k]
__device__ float  g_S[3*MTOT*OUTC];      // spline split-K partials [z][m][o]
__device__ float  g_Bc[MTOT*OUTC];       // base conv result        [m][o]

// ---------------- helpers ----------------
__device__ __forceinline__ uint32_t smem_u32(const void* p) {
    uint32_t a;
    asm("{ .reg .u64 t; cvta.to.shared.u64 t, %1; cvt.u32.u64 %0, t; }" : "=r"(a) : "l"(p));
    return a;
}
#define CPA16(sm, gp) asm volatile("cp.async.cg.shared.global [%0], [%1], 16;" :: "r"(sm), "l"(gp))
#define CP_COMMIT()   asm volatile("cp.async.commit_group;" ::: "memory")
#define CP_WAIT1()    asm volatile("cp.async.wait_group 1;" ::: "memory")
#define CP_WAIT0()    asm volatile("cp.async.wait_group 0;" ::: "memory")

__device__ __forceinline__ void mma16816(float* d, const uint32_t* a, const uint32_t* b) {
    asm volatile(
        "mma.sync.aligned.m16n8k16.row.col.f32.f16.f16.f32 "
        "{%0,%1,%2,%3}, {%4,%5,%6,%7}, {%8,%9}, {%0,%1,%2,%3};"
        : "+f"(d[0]), "+f"(d[1]), "+f"(d[2]), "+f"(d[3])
        : "r"(a[0]), "r"(a[1]), "r"(a[2]), "r"(a[3]), "r"(b[0]), "r"(b[1]));
}

// ---------------- knots / bspline ----------------
__device__ __forceinline__ float knot(int i) { return (float)(i - 3) * 0.4f - 1.0f; }

__device__ __forceinline__ void bspline8(float xv, float* out8) {
    float bb[11];
#pragma unroll
    for (int i = 0; i < 11; i++)
        bb[i] = (xv >= knot(i) && xv < knot(i + 1)) ? 1.0f : 0.0f;
    const float RK1 = 2.5f, RK2 = 1.25f, RK3 = 1.0f / 1.2f;
#pragma unroll
    for (int i = 0; i < 10; i++)
        bb[i] = (xv - knot(i)) * RK1 * bb[i] + (knot(i + 2) - xv) * RK1 * bb[i + 1];
#pragma unroll
    for (int i = 0; i < 9; i++)
        bb[i] = (xv - knot(i)) * RK2 * bb[i] + (knot(i + 3) - xv) * RK2 * bb[i + 1];
#pragma unroll
    for (int i = 0; i < 8; i++)
        bb[i] = (xv - knot(i)) * RK3 * bb[i] + (knot(i + 4) - xv) * RK3 * bb[i + 1];
#pragma unroll
    for (int i = 0; i < 8; i++) out8[i] = bb[i];
}

// ---------------- kernel 1: pack weights (vectorized, fp16) ----------------
__global__ void pack_kernel(const float* __restrict__ sw, const float* __restrict__ bw)
{
    int t = blockIdx.x * blockDim.x + threadIdx.x;
    const int NSPL = OUTC * INC * 9;     // 18432 (one thread per 8 f-values)
    const int NBAS = OUTC * KBAS;        // 18432
    if (t < NSPL) {
        int o = t / 288;
        int rem = t - o * 288;
        int c = rem / 9, tap = rem - c * 9;
        const float* src = sw + (size_t)(o * 288 + c * 9 + tap) * 8;
        float4 v0 = *(const float4*)(src);
        float4 v1 = *(const float4*)(src + 4);
        float vv[8] = {v0.x, v0.y, v0.z, v0.w, v1.x, v1.y, v1.z, v1.w};
        __half2 hh[4];
#pragma unroll
        for (int i = 0; i < 4; i++)
            hh[i] = __halves2half2(__float2half_rn(vv[2 * i]), __float2half_rn(vv[2 * i + 1]));
        *(uint4*)(g_wsh + (size_t)o * KSPL + tap * 256 + c * 8) = *(uint4*)hh;
    } else if (t < NSPL + NBAS) {
        int u = t - NSPL;
        int o = u / KBAS;
        int k = u - o * KBAS;            // k = tap*32 + c
        int tap = k >> 5, c = k & 31;
        g_wbh[u] = __float2half_rn(bw[(o * 32 + c) * 9 + tap]);
    }
}

// ---------------- kernel 2: basis fill over the PADDED grid ----------------
// Reference applies B-spline bases to padded zeros too (bases(0) != 0).
__global__ void fillpad_kernel(const float* __restrict__ x)
{
    int t = blockIdx.x * blockDim.x + threadIdx.x;
    if (t >= NPIX * 32) return;
    int c = t & 31;
    int pix = t >> 5;
    int w = pix % 58;
    int tmp = pix / 58;
    int h = tmp % 58;
    int b = tmp / 58;

    float xv = 0.0f;
    if (h >= 1 && h <= 56 && w >= 1 && w <= 56)
        xv = x[((b * 32 + c) * 56 + (h - 1)) * 56 + (w - 1)];

    float bb[8];
    bspline8(xv, bb);

    __half2 hh[4];
#pragma unroll
    for (int i = 0; i < 4; i++)
        hh[i] = __halves2half2(__float2half_rn(bb[2 * i]), __float2half_rn(bb[2 * i + 1]));
    *(uint4*)(g_fh + (size_t)pix * 256 + c * 8) = *(uint4*)hh;
    g_xph[pix * 32 + c] = __float2half_rn(xv);
}

// ---------------- kernel 3: split-K mma.sync GEMM (single-pass fp16) ----------------
// grid (196, 3): 588 uniform blocks (~4/SM), each does exactly 27 k=32 chunks.
// Tile M=64 N=64, 128 threads (2x2 warps). 3-stage cp.async pipeline, one
// __syncthreads per chunk. A and B both fp16-rounded (global err ~3e-4).
#define ASTRIDE 40   // halfs per smem row (80B, conflict-free)
#define NSTG 3

__global__ void __launch_bounds__(128) kan_mma_kernel()
{
    __shared__ __align__(16) __half sA[NSTG][64 * ASTRIDE];
    __shared__ __align__(16) __half sB[NSTG][64 * ASTRIDE];

    const int tid  = threadIdx.x;
    const int wid  = tid >> 5, lane = tid & 31;
    const int wm   = wid >> 1, wn = wid & 1;
    const int g    = lane >> 2, tg = lane & 3;
    const int mBase = blockIdx.x * 64;
    const int z     = blockIdx.y;
    const int chBase = z * CPB;

    const int lrow = tid >> 1;           // 0..63
    const int lsg0 = (tid & 1) * 2;      // 16B segs {0,1} or {2,3}
    int lm = mBase + lrow;
    int lb = lm / 3136; int lrem = lm - lb * 3136;
    int loh = lrem / 56, low = lrem - loh * 56;
    const int ppix = (lb * 58 + loh) * 58 + low;
    const uint32_t so0 = (uint32_t)(lrow * ASTRIDE + lsg0 * 8) * 2;

    float accS[2][4][4] = {};
    float accB[2][4][4] = {};

    auto load_stage = [&](int ch, int st) {
        const __half *ga, *gb;
        if (ch < NCH_S) {
            int tap = ch >> 3;
            int cf0 = (ch & 7) * 32;
            int toff = ((tap / 3) * 58 + (tap % 3)) * 256 + cf0;
            ga = g_fh + (size_t)ppix * 256 + toff;
            gb = g_wsh + lrow * KSPL + ch * 32;
        } else {
            int tap = ch - NCH_S;
            int toff = ((tap / 3) * 58 + (tap % 3)) * 32;
            ga = g_xph + (size_t)ppix * 32 + toff;
            gb = g_wbh + lrow * KBAS + tap * 32;
        }
        uint32_t a = smem_u32(&sA[st][0]) + so0;
        uint32_t b = smem_u32(&sB[st][0]) + so0;
#pragma unroll
        for (int s = 0; s < 2; s++) {
            int e = (lsg0 + s) * 8;
            CPA16(a + s * 16, ga + e);
            CPA16(b + s * 16, gb + e);
        }
    };

    auto do_chunk = [&](float (&acc)[2][4][4], int st) {
        const __half* A = sA[st];
        const __half* B = sB[st];
#pragma unroll
        for (int k0 = 0; k0 < 32; k0 += 16) {
            uint32_t a[2][4], b[4][2];
            const int cb = k0 + 2 * tg;
#pragma unroll
            for (int mi = 0; mi < 2; mi++) {
                int r = wm * 32 + mi * 16 + g;
                a[mi][0] = *(const uint32_t*)&A[r * ASTRIDE + cb];
                a[mi][1] = *(const uint32_t*)&A[(r + 8) * ASTRIDE + cb];
                a[mi][2] = *(const uint32_t*)&A[r * ASTRIDE + cb + 8];
                a[mi][3] = *(const uint32_t*)&A[(r + 8) * ASTRIDE + cb + 8];
            }
#pragma unroll
            for (int nj = 0; nj < 4; nj++) {
                int n = wn * 32 + nj * 8 + g;
                b[nj][0] = *(const uint32_t*)&B[n * ASTRIDE + cb];
                b[nj][1] = *(const uint32_t*)&B[n * ASTRIDE + cb + 8];
            }
#pragma unroll
            for (int mi = 0; mi < 2; mi++)
#pragma unroll
                for (int nj = 0; nj < 4; nj++)
                    mma16816(acc[mi][nj], a[mi], b[nj]);
        }
    };

    // 3-stage pipeline: prefetch 2, one sync per chunk
    load_stage(chBase, 0);
    CP_COMMIT();
    load_stage(chBase + 1, 1);
    CP_COMMIT();
    for (int i = 0; i < CPB; i++) {
        int ch = chBase + i;
        int st = i % NSTG;
        if (i + 2 < CPB) CP_WAIT1();
        else             CP_WAIT0();
        __syncthreads();            // stage st ready; all threads done with stage (i-1)%NSTG
        if (i + 2 < CPB) {
            load_stage(ch + 2, (i + 2) % NSTG);
            CP_COMMIT();
        }
        if (ch < NCH_S) do_chunk(accS, st);
        else            do_chunk(accB, st);
    }

    // ---- store partials [m][o]; z==2 also stores base result ----
    float* Sp = g_S + (size_t)z * MTOT * 64;
#pragma unroll
    for (int mi = 0; mi < 2; mi++) {
#pragma unroll
        for (int gg = 0; gg < 2; gg++) {
            int row = wm * 32 + mi * 16 + g + gg * 8;
            size_t m = mBase + row;
#pragma unroll
            for (int nj = 0; nj < 4; nj++) {
                int o0 = wn * 32 + nj * 8 + 2 * tg;
                *(float2*)&Sp[m * 64 + o0] =
                    make_float2(accS[mi][nj][gg * 2], accS[mi][nj][gg * 2 + 1]);
                if (z == 2)
                    *(float2*)&g_Bc[m * 64 + o0] =
                        make_float2(accB[mi][nj][gg * 2], accB[mi][nj][gg * 2 + 1]);
            }
        }
    }
}

// ---------------- kernel 4: reduce + silu + scaler epilogue (R8 version) ----------------
// Block = 64 m-pixels x 64 o. Coalesced reads over o, smem transpose,
// coalesced writes over m. 3136 = 49*64 -> blocks never straddle images.
__global__ void __launch_bounds__(256) reduce_kernel(const float* __restrict__ scaler,
                                                     float* __restrict__ out)
{
    __shared__ float T[64][65];
    const int tid = threadIdx.x;
    const int mBase = blockIdx.x * 64;
    const int b = mBase / 3136, ssp0 = mBase - b * 3136;

    {   // phase 1: read [m][o] coalesced, compute, store transposed
        const int ml0 = tid >> 4;             // 0..15
        const int o4  = (tid & 15) * 4;
        float4 sc4 = *(const float4*)(scaler + o4);
        const float scv[4] = {sc4.x, sc4.y, sc4.z, sc4.w};
#pragma unroll
        for (int r = 0; r < 4; r++) {
            int ml = ml0 + r * 16;
            size_t m = mBase + ml;
            float4 s0 = *(const float4*)&g_S[m * 64 + o4];
            float4 s1 = *(const float4*)&g_S[((size_t)MTOT + m) * 64 + o4];
            float4 s2 = *(const float4*)&g_S[((size_t)2 * MTOT + m) * 64 + o4];
            float4 bv = *(const float4*)&g_Bc[m * 64 + o4];
            float ss[4] = {s0.x + s1.x + s2.x, s0.y + s1.y + s2.y,
                           s0.z + s1.z + s2.z, s0.w + s1.w + s2.w};
            float bb[4] = {bv.x, bv.y, bv.z, bv.w};
#pragma unroll
            for (int j = 0; j < 4; j++) {
                float silu = bb[j] / (1.0f + expf(-bb[j]));
                T[o4 + j][ml] = silu + scv[j] * ss[j];
            }
        }
    }
    __syncthreads();
    {   // phase 2: write [o][m] coalesced
        const int ol0  = tid >> 4;            // 0..15
        const int mseg = (tid & 15) * 4;
#pragma unroll
        for (int r = 0; r < 4; r++) {
            int o = ol0 + r * 16;
            float4 v = make_float4(T[o][mseg], T[o][mseg + 1], T[o][mseg + 2], T[o][mseg + 3]);
            *(float4*)(out + ((size_t)(b * 64 + o)) * 3136 + ssp0 + mseg) = v;
        }
    }
}

// ---------------- launch ----------------
extern "C" void kernel_launch(void* const* d_in, const int* in_sizes, int n_in,
                              void* d_out, int out_size)
{
    const float* x  = (const float*)d_in[0];  // (4,32,56,56)
    const float* bw = (const float*)d_in[1];  // (64,32,3,3)
    const float* sw = (const float*)d_in[2];  // (64,288,8)
    const float* sc = (const float*)d_in[3];  // (64,)
    float* out = (float*)d_out;               // (4,64,56,56)

    {   // 1. pack weights (fp16, [o][k])
        int total = OUTC * INC * 9 + OUTC * KBAS;
        pack_kernel<<<(total + 255) / 256, 256>>>(sw, bw);
    }
    {   // 2. basis expansion over the padded grid
        int total = NPIX * 32;
        fillpad_kernel<<<(total + 255) / 256, 256>>>(x);
    }
    {   // 3. split-K GEMM: 588 uniform blocks (~4/SM), single-pass fp16
        dim3 grid(MTOT / 64, 3);
        kan_mma_kernel<<<grid, 128>>>();
    }
    {   // 4. reduce + silu + scaler + store
        reduce_kernel<<<MTOT / 64, 256>>>(sc, out);
    }
}